// round 1
// baseline (speedup 1.0000x reference)
#include <cuda_runtime.h>
#include <math.h>

#define NN   50000
#define EE   800000
#define CC   64
#define FE   16
#define NLAY 7
#define GG   512
#define NCLSV 10
#define EPSV 1e-5f

// ---------------- static device scratch (no allocations allowed) ----------------
__device__ float  g_w[NLAY * EE];        // per-layer edge weights (edge order)
__device__ float  g_dis[NLAY * NN];      // deg accum -> rsqrt(deg+1) in place
__device__ float  g_norm[NLAY * EE];     // gcn_norm coeffs in CSR order
__device__ int    g_off[NN + 1];
__device__ int    g_cnt[NN];
__device__ int    g_cnt2[NN];
__device__ int    g_pos[EE];
__device__ int    g_src[EE];             // CSR source row per slot
__device__ float  g_bufA[NN * CC];
__device__ float  g_bufB[NN * CC];
__device__ float  g_bufC[NN * CC];
__device__ float  g_bufD[NN * CC];
__device__ float  g_xl[NN * CC];
__device__ double g_bn[6 * 2 * CC];      // 6 batchnorms x (sum, sumsq) x 64 ch
__device__ unsigned g_pool[GG * CC];

// ---------------- init / zero ----------------
__global__ void k_zero() {
    int i = blockIdx.x * blockDim.x + threadIdx.x;
    if (i < NN) { g_cnt[i] = 0; g_cnt2[i] = 0; }
    if (i < NLAY * NN) g_dis[i] = 0.f;
    if (i < GG * CC) g_pool[i] = 0u;
    if (i < 6 * 2 * CC) g_bn[i] = 0.0;
}

// ---------------- CSR build ----------------
__global__ void k_count(const int* __restrict__ col) {
    int e = blockIdx.x * blockDim.x + threadIdx.x;
    if (e < EE) atomicAdd(&g_cnt[col[e]], 1);
}

__global__ void k_scan() {
    __shared__ int sums[1024];
    const int CH = (NN + 1023) / 1024;  // 49
    int t = threadIdx.x;
    int base = t * CH;
    int s = 0;
    for (int i = 0; i < CH; i++) {
        int idx = base + i;
        if (idx < NN) s += g_cnt[idx];
    }
    sums[t] = s;
    __syncthreads();
    for (int off = 1; off < 1024; off <<= 1) {
        int v = 0;
        if (t >= off) v = sums[t - off];
        __syncthreads();
        sums[t] += v;
        __syncthreads();
    }
    int excl = (t == 0) ? 0 : sums[t - 1];
    for (int i = 0; i < CH; i++) {
        int idx = base + i;
        if (idx < NN) {
            int c = g_cnt[idx];
            g_off[idx] = excl;
            excl += c;
        }
    }
    if (t == 1023) g_off[NN] = excl;
}

__global__ void k_fill(const int* __restrict__ row, const int* __restrict__ col) {
    int e = blockIdx.x * blockDim.x + threadIdx.x;
    if (e < EE) {
        int c = col[e];
        int p = g_off[c] + atomicAdd(&g_cnt2[c], 1);
        g_pos[e] = p;
        g_src[p] = row[e];
    }
}

// ---------------- edge MLPs (all 7 layers fused) ----------------
struct MlpP { const float* w1; const float* b1; const float* w2; const float* b2; };
struct MlpAll { MlpP p[NLAY]; };

__global__ void k_mlp(const float* __restrict__ ea, const int* __restrict__ col, MlpAll mp) {
    __shared__ float sw1[NLAY][FE][FE];
    __shared__ float sb1[NLAY][FE];
    __shared__ float sw2[NLAY][FE];
    __shared__ float sb2[NLAY];
    int t = threadIdx.x;
    for (int l = 0; l < NLAY; l++) {
        for (int i = t; i < FE * FE; i += blockDim.x) sw1[l][i / FE][i % FE] = mp.p[l].w1[i];
        if (t < FE) { sb1[l][t] = mp.p[l].b1[t]; sw2[l][t] = mp.p[l].w2[t]; }
        if (t == 0) sb2[l] = mp.p[l].b2[0];
    }
    __syncthreads();
    int e = blockIdx.x * blockDim.x + t;
    if (e >= EE) return;
    float a[FE];
    const float4* ea4 = (const float4*)(ea + (size_t)e * FE);
#pragma unroll
    for (int q = 0; q < 4; q++) {
        float4 v = ea4[q];
        a[4 * q] = v.x; a[4 * q + 1] = v.y; a[4 * q + 2] = v.z; a[4 * q + 3] = v.w;
    }
    int c = col[e];
#pragma unroll 1
    for (int l = 0; l < NLAY; l++) {
        float s = sb2[l];
#pragma unroll
        for (int j = 0; j < FE; j++) {
            float h = sb1[l][j];
#pragma unroll
            for (int k = 0; k < FE; k++) h += a[k] * sw1[l][j][k];
            h = fmaxf(h, 0.f);
            s += h * sw2[l][j];
        }
        float wv = 1.f / (1.f + expf(-s));
        g_w[l * EE + e] = wv;
        atomicAdd(&g_dis[l * NN + c], wv);
    }
}

__global__ void k_dis() {
    int i = blockIdx.x * blockDim.x + threadIdx.x;
    if (i < NLAY * NN) g_dis[i] = rsqrtf(g_dis[i] + 1.0f);  // deg includes self-loop weight 1
}

__global__ void k_norm(const int* __restrict__ row, const int* __restrict__ col) {
    int e = blockIdx.x * blockDim.x + threadIdx.x;
    if (e >= EE) return;
    int r = row[e], c = col[e], p = g_pos[e];
#pragma unroll 1
    for (int l = 0; l < NLAY; l++) {
        g_norm[l * EE + p] = g_dis[l * NN + r] * g_w[l * EE + e] * g_dis[l * NN + c];
    }
}

// ---------------- batchnorm stats (double accumulate) ----------------
__global__ void k_bnstats(const float* __restrict__ x, double* __restrict__ out) {
    int t = threadIdx.x;
    int c = t & 63;
    float s = 0.f, q = 0.f;
    for (int r = blockIdx.x * 4 + (t >> 6); r < NN; r += gridDim.x * 4) {
        float v = x[r * CC + c];
        s += v; q += v * v;
    }
    __shared__ float ss[256], qq[256];
    ss[t] = s; qq[t] = q;
    __syncthreads();
    if (t < 64) {
        s = ss[t] + ss[t + 64] + ss[t + 128] + ss[t + 192];
        q = qq[t] + qq[t + 64] + qq[t + 128] + qq[t + 192];
        atomicAdd(&out[c], (double)s);
        atomicAdd(&out[CC + c], (double)q);
    }
}

// ---------------- node transform GEMM: out = act(x) @ lw^T ----------------
// lw layout [out_c][in_k] row-major. Optional fused batchnorm+relu on input.
__global__ void k_gemm(const float* __restrict__ x, const float* __restrict__ lw,
                       float* __restrict__ out, const double* __restrict__ bns) {
    __shared__ __align__(16) float swt[CC][CC + 4];  // swt[k][c]
    __shared__ __align__(16) float sx[CC][CC + 4];   // sx[r][k]
    __shared__ float smu[CC], sinv[CC];
    int t = threadIdx.x;
#pragma unroll
    for (int i = 0; i < 16; i++) {
        int e = t + 256 * i;
        int c = e >> 6, k = e & 63;
        swt[k][c] = lw[e];
    }
    if (bns != nullptr && t < CC) {
        double mu = bns[t] * (1.0 / NN);
        double var = bns[CC + t] * (1.0 / NN) - mu * mu;
        smu[t] = (float)mu;
        sinv[t] = rsqrtf((float)var + EPSV);
    }
    __syncthreads();
    int row0 = blockIdx.x * 64;
#pragma unroll
    for (int i = 0; i < 16; i++) {
        int e = i * 256 + t;
        int r = e >> 6, k = e & 63;
        int gr = row0 + r;
        float v = (gr < NN) ? x[gr * CC + k] : 0.f;
        if (bns != nullptr) v = fmaxf((v - smu[k]) * sinv[k], 0.f);
        sx[r][k] = v;
    }
    __syncthreads();
    int r = t >> 2;
    int cb = (t & 3) * 4;
    float acc[16];
#pragma unroll
    for (int i = 0; i < 16; i++) acc[i] = 0.f;
    for (int k = 0; k < CC; k++) {
        float a = sx[r][k];
#pragma unroll
        for (int j = 0; j < 4; j++) {
            float4 b = *(const float4*)&swt[k][cb + j * 16];
            acc[j * 4 + 0] += a * b.x;
            acc[j * 4 + 1] += a * b.y;
            acc[j * 4 + 2] += a * b.z;
            acc[j * 4 + 3] += a * b.w;
        }
    }
    int gr = row0 + r;
    if (gr < NN) {
#pragma unroll
        for (int j = 0; j < 4; j++) {
            *(float4*)&out[gr * CC + cb + j * 16] =
                make_float4(acc[j * 4], acc[j * 4 + 1], acc[j * 4 + 2], acc[j * 4 + 3]);
        }
    }
}

// ---------------- message gather (warp per node, no atomics) ----------------
__global__ void k_gather(int l, const float* __restrict__ xl, float* __restrict__ out) {
    int gw = (blockIdx.x * blockDim.x + threadIdx.x) >> 5;
    int lane = threadIdx.x & 31;
    if (gw >= NN) return;
    const float2* x2 = (const float2*)xl;
    float d = g_dis[l * NN + gw];
    float2 v0 = x2[gw * 32 + lane];
    float ax = v0.x * d * d;   // self-loop: weight 1, norm = dis^2
    float ay = v0.y * d * d;
    int s = g_off[gw], en = g_off[gw + 1];
    const float* nl = g_norm + (size_t)l * EE;
    for (int j0 = s; j0 < en; j0 += 32) {
        int rem = en - j0;
        int idx = j0 + lane;
        int r = (lane < rem) ? g_src[idx] : 0;
        float nm = (lane < rem) ? nl[idx] : 0.f;
        int cnt = rem < 32 ? rem : 32;
        for (int k = 0; k < cnt; k++) {
            int rr = __shfl_sync(0xffffffffu, r, k);
            float nn = __shfl_sync(0xffffffffu, nm, k);
            float2 v = x2[rr * 32 + lane];
            ax += v.x * nn;
            ay += v.y * nn;
        }
    }
    float2 o; o.x = ax; o.y = ay;
    ((float2*)out)[gw * 32 + lane] = o;
}

// ---------------- elementwise add ----------------
__global__ void k_add(const float* __restrict__ a, const float* __restrict__ b,
                      float* __restrict__ o) {
    int i = blockIdx.x * blockDim.x + threadIdx.x;
    if (i < NN * CC) o[i] = a[i] + b[i];
}

// ---------------- pooling: relu(xc+xa+xd) -> segment max ----------------
__global__ void k_pool(const float* __restrict__ xc, const float* __restrict__ xa,
                       const float* __restrict__ xd, const int* __restrict__ batch) {
    int i = blockIdx.x * blockDim.x + threadIdx.x;
    if (i >= NN * CC) return;
    int n = i >> 6, c = i & 63;
    float v = fmaxf(xc[i] + xa[i] + xd[i], 0.f);
    atomicMax(&g_pool[batch[n] * CC + c], __float_as_uint(v));
}

// ---------------- final linear ----------------
__global__ void k_fin(const float* __restrict__ lw, const float* __restrict__ lb,
                      float* __restrict__ out) {
    __shared__ float sw[NCLSV * CC];
    __shared__ float sb[NCLSV];
    int t = threadIdx.x;
    for (int i = t; i < NCLSV * CC; i += blockDim.x) sw[i] = lw[i];
    if (t < NCLSV) sb[t] = lb[t];
    __syncthreads();
    int g = blockIdx.x * blockDim.x + t;
    if (g >= GG) return;
    float acc[NCLSV];
#pragma unroll
    for (int j = 0; j < NCLSV; j++) acc[j] = sb[j];
    for (int k = 0; k < CC; k++) {
        float p = __uint_as_float(g_pool[g * CC + k]);
#pragma unroll
        for (int j = 0; j < NCLSV; j++) acc[j] += p * sw[j * CC + k];
    }
#pragma unroll
    for (int j = 0; j < NCLSV; j++) out[g * NCLSV + j] = acc[j];
}

// ---------------- host launcher ----------------
extern "C" void kernel_launch(void* const* d_in, const int* in_sizes, int n_in,
                              void* d_out, int out_size) {
    const float* x      = (const float*)d_in[0];
    const int*   ei     = (const int*)d_in[1];
    const int*   batch  = (const int*)d_in[2];
    // d_in[3] = dropout (unused, eval mode)
    const float* ea     = (const float*)d_in[4];
    const float* c1_lw  = (const float*)d_in[5];
    const float* c1_w1  = (const float*)d_in[6];
    const float* c1_b1  = (const float*)d_in[7];
    const float* c1_w2  = (const float*)d_in[8];
    const float* c1_b2  = (const float*)d_in[9];
    const float* h1_lw  = (const float*)d_in[10];
    const float* h1_w1  = (const float*)d_in[11];
    const float* h1_b1  = (const float*)d_in[12];
    const float* h1_w2  = (const float*)d_in[13];
    const float* h1_b2  = (const float*)d_in[14];
    const float* h2_lw  = (const float*)d_in[15];
    const float* h2_w1  = (const float*)d_in[16];
    const float* h2_b1  = (const float*)d_in[17];
    const float* h2_w2  = (const float*)d_in[18];
    const float* h2_b2  = (const float*)d_in[19];
    const float* lin_w  = (const float*)d_in[20];
    const float* lin_b  = (const float*)d_in[21];

    const int* row = ei;
    const int* col = ei + EE;

    float *A, *B, *C, *D, *XL;
    double* BN;
    cudaGetSymbolAddress((void**)&A,  g_bufA);
    cudaGetSymbolAddress((void**)&B,  g_bufB);
    cudaGetSymbolAddress((void**)&C,  g_bufC);
    cudaGetSymbolAddress((void**)&D,  g_bufD);
    cudaGetSymbolAddress((void**)&XL, g_xl);
    cudaGetSymbolAddress((void**)&BN, g_bn);

    const int EB = (EE + 255) / 256;
    const int ZB = (NLAY * NN + 255) / 256;

    k_zero<<<ZB, 256>>>();
    k_count<<<EB, 256>>>(col);
    k_scan<<<1, 1024>>>();
    k_fill<<<EB, 256>>>(row, col);

    MlpAll mp;
    mp.p[0] = {c1_w1, c1_b1, c1_w2, c1_b2};
    for (int i = 0; i < 3; i++) {
        mp.p[1 + i] = {h1_w1 + i * FE * FE, h1_b1 + i * FE, h1_w2 + i * FE, h1_b2 + i};
        mp.p[4 + i] = {h2_w1 + i * FE * FE, h2_b1 + i * FE, h2_w2 + i * FE, h2_b2 + i};
    }
    k_mlp<<<EB, 256>>>(ea, col, mp);
    k_dis<<<ZB, 256>>>();
    k_norm<<<EB, 256>>>(row, col);

    const int GEMM_B = (NN + 63) / 64;           // 782
    const int GATH_B = (NN * 32 + 255) / 256;    // 6250
    const int ADD_B  = (NN * CC + 255) / 256;

    auto conv = [&](int l, const float* xin, float* xout, double* bns, const float* lwp) {
        if (bns) k_bnstats<<<128, 256>>>(xin, bns);
        k_gemm<<<GEMM_B, 256>>>(xin, lwp, XL, bns);
        k_gather<<<GATH_B, 256>>>(l, XL, xout);
    };

    conv(0, x, A, nullptr, c1_lw);                       // conv1 -> x0 in A
    conv(1, A, B, BN + 0 * 128, h1_lw + 0 * CC * CC);
    conv(2, B, C, BN + 1 * 128, h1_lw + 1 * CC * CC);
    conv(3, C, B, BN + 2 * 128, h1_lw + 2 * CC * CC);
    k_add<<<ADD_B, 256>>>(B, A, D);                      // x1 in D (== new x)
    conv(4, D, C, BN + 3 * 128, h2_lw + 0 * CC * CC);
    conv(5, C, B, BN + 4 * 128, h2_lw + 1 * CC * CC);
    conv(6, B, C, BN + 5 * 128, h2_lw + 2 * CC * CC);
    k_pool<<<ADD_B, 256>>>(C, A, D, batch);              // relu(x + x0 + x1), segment max
    k_fin<<<2, 256>>>(lin_w, lin_b, (float*)d_out);
}

// round 2
// speedup vs baseline: 1.1361x; 1.1361x over previous
#include <cuda_runtime.h>
#include <math.h>

#define NN    50000
#define EE    800000
#define CC    64
#define FE    16
#define NLAY  7
#define GG    512
#define NCLSV 10
#define EPSV  1e-5f

// ---------------- static device scratch ----------------
__device__ float  g_w2[EE * 8];           // per-edge weights, [e][8] (7 layers + pad)
__device__ float  g_dis2[NN * 8];         // [node][8]: deg accum -> rsqrt(deg+1)
__device__ int2   g_epk[NLAY * EE];       // CSR slot -> (src, norm_bits) per layer
__device__ int    g_off[NN + 1];
__device__ int    g_cnt[NN];
__device__ int    g_cnt2[NN];
__device__ float  g_bufA[NN * CC];
__device__ float  g_bufB[NN * CC];
__device__ float  g_bufC[NN * CC];
__device__ float  g_bufD[NN * CC];
__device__ float  g_xl[NN * CC];
__device__ double g_bn[6 * 2 * CC];       // 6 BN slots x (sum[64], sumsq[64])
__device__ unsigned g_pool[GG * CC];

// ---------------- zero ----------------
__global__ void k_zero() {
    int i = blockIdx.x * blockDim.x + threadIdx.x;
    if (i < NN) { g_cnt[i] = 0; g_cnt2[i] = 0; }
    if (i < NN * 8) g_dis2[i] = 0.f;
    if (i < GG * CC) g_pool[i] = 0u;
    if (i < 6 * 2 * CC) g_bn[i] = 0.0;
}

// ---------------- edge MLPs (7 layers) + degree accum + CSR count ----------------
struct MlpP { const float* w1; const float* b1; const float* w2; const float* b2; };
struct MlpAll { MlpP p[NLAY]; };

__global__ void k_mlp(const float* __restrict__ ea, const int* __restrict__ col, MlpAll mp) {
    __shared__ float sw1[NLAY][FE][FE];
    __shared__ float sb1[NLAY][FE];
    __shared__ float sw2[NLAY][FE];
    __shared__ float sb2[NLAY];
    int t = threadIdx.x;
    for (int l = 0; l < NLAY; l++) {
        for (int i = t; i < FE * FE; i += blockDim.x) sw1[l][i / FE][i % FE] = mp.p[l].w1[i];
        if (t < FE) { sb1[l][t] = mp.p[l].b1[t]; sw2[l][t] = mp.p[l].w2[t]; }
        if (t == 0) sb2[l] = mp.p[l].b2[0];
    }
    __syncthreads();
    int e = blockIdx.x * blockDim.x + t;
    if (e >= EE) return;
    float a[FE];
    const float4* ea4 = (const float4*)(ea + (size_t)e * FE);
#pragma unroll
    for (int q = 0; q < 4; q++) {
        float4 v = ea4[q];
        a[4 * q] = v.x; a[4 * q + 1] = v.y; a[4 * q + 2] = v.z; a[4 * q + 3] = v.w;
    }
    int c = col[e];
    float wv[8];
    wv[7] = 0.f;
#pragma unroll 1
    for (int l = 0; l < NLAY; l++) {
        float s = sb2[l];
#pragma unroll
        for (int j = 0; j < FE; j++) {
            float h = sb1[l][j];
#pragma unroll
            for (int k = 0; k < FE; k++) h += a[k] * sw1[l][j][k];
            h = fmaxf(h, 0.f);
            s += h * sw2[l][j];
        }
        float w = 1.f / (1.f + expf(-s));
        wv[l] = w;
        atomicAdd(&g_dis2[c * 8 + l], w);
    }
    float4* wo = (float4*)&g_w2[(size_t)e * 8];
    wo[0] = make_float4(wv[0], wv[1], wv[2], wv[3]);
    wo[1] = make_float4(wv[4], wv[5], wv[6], wv[7]);
    atomicAdd(&g_cnt[c], 1);
}

// ---------------- CSR offsets (single-block scan) ----------------
__global__ void k_scan() {
    __shared__ int sums[1024];
    const int CH = (NN + 1023) / 1024;
    int t = threadIdx.x;
    int base = t * CH;
    int s = 0;
    for (int i = 0; i < CH; i++) {
        int idx = base + i;
        if (idx < NN) s += g_cnt[idx];
    }
    sums[t] = s;
    __syncthreads();
    for (int off = 1; off < 1024; off <<= 1) {
        int v = 0;
        if (t >= off) v = sums[t - off];
        __syncthreads();
        sums[t] += v;
        __syncthreads();
    }
    int excl = (t == 0) ? 0 : sums[t - 1];
    for (int i = 0; i < CH; i++) {
        int idx = base + i;
        if (idx < NN) {
            int c = g_cnt[idx];
            g_off[idx] = excl;
            excl += c;
        }
    }
    if (t == 1023) g_off[NN] = excl;
}

__global__ void k_dis() {
    int i = blockIdx.x * blockDim.x + threadIdx.x;
    if (i < NN * 8) g_dis2[i] = rsqrtf(g_dis2[i] + 1.0f);  // +1 = self-loop weight
}

// ---------------- CSR fill + gcn_norm coefficients (fused) ----------------
__global__ void k_fillnorm(const int* __restrict__ row, const int* __restrict__ col) {
    int e = blockIdx.x * blockDim.x + threadIdx.x;
    if (e >= EE) return;
    int r = row[e], c = col[e];
    int p = g_off[c] + atomicAdd(&g_cnt2[c], 1);
    float4 w0 = *(const float4*)&g_w2[(size_t)e * 8];
    float4 w1 = *(const float4*)&g_w2[(size_t)e * 8 + 4];
    float4 dr0 = *(const float4*)&g_dis2[r * 8];
    float4 dr1 = *(const float4*)&g_dis2[r * 8 + 4];
    float4 dc0 = *(const float4*)&g_dis2[c * 8];
    float4 dc1 = *(const float4*)&g_dis2[c * 8 + 4];
    float w[7]  = {w0.x, w0.y, w0.z, w0.w, w1.x, w1.y, w1.z};
    float dr[7] = {dr0.x, dr0.y, dr0.z, dr0.w, dr1.x, dr1.y, dr1.z};
    float dc[7] = {dc0.x, dc0.y, dc0.z, dc0.w, dc1.x, dc1.y, dc1.z};
#pragma unroll
    for (int l = 0; l < NLAY; l++)
        g_epk[(size_t)l * EE + p] = make_int2(r, __float_as_int(dr[l] * w[l] * dc[l]));
}

// ---------------- node transform GEMM: out = act(x) @ lw^T ----------------
__global__ void k_gemm(const float* __restrict__ x, const float* __restrict__ lw,
                       float* __restrict__ out, const double* __restrict__ bns) {
    __shared__ __align__(16) float swt[CC][CC + 4];
    __shared__ __align__(16) float sx[CC][CC + 4];
    __shared__ float smu[CC], sinv[CC];
    int t = threadIdx.x;
#pragma unroll
    for (int i = 0; i < 16; i++) {
        int e = t + 256 * i;
        int c = e >> 6, k = e & 63;
        swt[k][c] = lw[e];
    }
    if (bns != nullptr && t < CC) {
        double mu = bns[t] * (1.0 / NN);
        double var = bns[CC + t] * (1.0 / NN) - mu * mu;
        smu[t] = (float)mu;
        sinv[t] = rsqrtf((float)var + EPSV);
    }
    __syncthreads();
    int row0 = blockIdx.x * 64;
#pragma unroll
    for (int i = 0; i < 16; i++) {
        int e = i * 256 + t;
        int r = e >> 6, k = e & 63;
        int gr = row0 + r;
        float v = (gr < NN) ? x[gr * CC + k] : 0.f;
        if (bns != nullptr) v = fmaxf((v - smu[k]) * sinv[k], 0.f);
        sx[r][k] = v;
    }
    __syncthreads();
    int r = t >> 2;
    int cb = (t & 3) * 4;
    float acc[16];
#pragma unroll
    for (int i = 0; i < 16; i++) acc[i] = 0.f;
    for (int k = 0; k < CC; k++) {
        float a = sx[r][k];
#pragma unroll
        for (int j = 0; j < 4; j++) {
            float4 b = *(const float4*)&swt[k][cb + j * 16];
            acc[j * 4 + 0] += a * b.x;
            acc[j * 4 + 1] += a * b.y;
            acc[j * 4 + 2] += a * b.z;
            acc[j * 4 + 3] += a * b.w;
        }
    }
    int gr = row0 + r;
    if (gr < NN) {
#pragma unroll
        for (int j = 0; j < 4; j++)
            *(float4*)&out[gr * CC + cb + j * 16] =
                make_float4(acc[j * 4], acc[j * 4 + 1], acc[j * 4 + 2], acc[j * 4 + 3]);
    }
}

// ---------------- message gather: warp/node, 4-deep pipelined, fused epilogues ----------------
// mode 0: out = acc; mode 1: out = acc + skipA; mode 2: pool relu(acc+skipA+skipB)
__global__ void __launch_bounds__(512) k_gather(
    int l, const float2* __restrict__ x2, float* __restrict__ out,
    const float* __restrict__ skipA, const float* __restrict__ skipB,
    const int* __restrict__ batch, int mode, int statslot)
{
    __shared__ float s_s[64], s_q[64];
    int t = threadIdx.x;
    bool dostats = statslot >= 0;
    if (dostats) {
        if (t < 64) { s_s[t] = 0.f; s_q[t] = 0.f; }
        __syncthreads();
    }
    int node = blockIdx.x * 16 + (t >> 5);
    int lane = t & 31;
    float vx = 0.f, vy = 0.f;
    // (3125 * 16 == 50000: no out-of-range nodes)
    {
        float d = g_dis2[node * 8 + l];
        float2 v0 = x2[node * 32 + lane];
        float dd = d * d;
        float ax = v0.x * dd, ay = v0.y * dd;
        int s0 = g_off[node], e0 = g_off[node + 1];
        const int2* ep = g_epk + (size_t)l * EE;
        for (int j0 = s0; j0 < e0; j0 += 32) {
            int idx = j0 + lane;
            int2 pk = (idx < e0) ? ep[idx] : make_int2(0, 0);
            int cnt = e0 - j0; if (cnt > 32) cnt = 32;
            int cntp = (cnt + 3) & ~3;
            for (int k = 0; k < cntp; k += 4) {
                int r0 = __shfl_sync(0xffffffffu, pk.x, k);
                int r1 = __shfl_sync(0xffffffffu, pk.x, k + 1);
                int r2 = __shfl_sync(0xffffffffu, pk.x, k + 2);
                int r3 = __shfl_sync(0xffffffffu, pk.x, k + 3);
                float n0 = __int_as_float(__shfl_sync(0xffffffffu, pk.y, k));
                float n1 = __int_as_float(__shfl_sync(0xffffffffu, pk.y, k + 1));
                float n2 = __int_as_float(__shfl_sync(0xffffffffu, pk.y, k + 2));
                float n3 = __int_as_float(__shfl_sync(0xffffffffu, pk.y, k + 3));
                float2 w0 = x2[r0 * 32 + lane];
                float2 w1 = x2[r1 * 32 + lane];
                float2 w2 = x2[r2 * 32 + lane];
                float2 w3 = x2[r3 * 32 + lane];
                ax = fmaf(w0.x, n0, ax); ay = fmaf(w0.y, n0, ay);
                ax = fmaf(w1.x, n1, ax); ay = fmaf(w1.y, n1, ay);
                ax = fmaf(w2.x, n2, ax); ay = fmaf(w2.y, n2, ay);
                ax = fmaf(w3.x, n3, ax); ay = fmaf(w3.y, n3, ay);
            }
        }
        int base = node * 64 + lane * 2;
        vx = ax; vy = ay;
        if (mode == 1) { vx += skipA[base]; vy += skipA[base + 1]; }
        if (mode == 2) {
            vx = fmaxf(ax + skipA[base] + skipB[base], 0.f);
            vy = fmaxf(ay + skipA[base + 1] + skipB[base + 1], 0.f);
            int g = batch[node];
            atomicMax(&g_pool[g * CC + lane * 2], __float_as_uint(vx));
            atomicMax(&g_pool[g * CC + lane * 2 + 1], __float_as_uint(vy));
        } else {
            float2 o; o.x = vx; o.y = vy;
            ((float2*)out)[node * 32 + lane] = o;
        }
    }
    if (dostats) {
        atomicAdd(&s_s[lane * 2], vx);
        atomicAdd(&s_s[lane * 2 + 1], vy);
        atomicAdd(&s_q[lane * 2], vx * vx);
        atomicAdd(&s_q[lane * 2 + 1], vy * vy);
        __syncthreads();
        if (t < 64) {
            atomicAdd(&g_bn[statslot * 128 + t], (double)s_s[t]);
            atomicAdd(&g_bn[statslot * 128 + 64 + t], (double)s_q[t]);
        }
    }
}

// ---------------- final linear ----------------
__global__ void k_fin(const float* __restrict__ lw, const float* __restrict__ lb,
                      float* __restrict__ out) {
    __shared__ float sw[NCLSV * CC];
    __shared__ float sb[NCLSV];
    int t = threadIdx.x;
    for (int i = t; i < NCLSV * CC; i += blockDim.x) sw[i] = lw[i];
    if (t < NCLSV) sb[t] = lb[t];
    __syncthreads();
    int g = blockIdx.x * blockDim.x + t;
    if (g >= GG) return;
    float acc[NCLSV];
#pragma unroll
    for (int j = 0; j < NCLSV; j++) acc[j] = sb[j];
    for (int k = 0; k < CC; k++) {
        float p = __uint_as_float(g_pool[g * CC + k]);
#pragma unroll
        for (int j = 0; j < NCLSV; j++) acc[j] += p * sw[j * CC + k];
    }
#pragma unroll
    for (int j = 0; j < NCLSV; j++) out[g * NCLSV + j] = acc[j];
}

// ---------------- host launcher ----------------
extern "C" void kernel_launch(void* const* d_in, const int* in_sizes, int n_in,
                              void* d_out, int out_size) {
    const float* x      = (const float*)d_in[0];
    const int*   ei     = (const int*)d_in[1];
    const int*   batch  = (const int*)d_in[2];
    const float* ea     = (const float*)d_in[4];
    const float* c1_lw  = (const float*)d_in[5];
    const float* c1_w1  = (const float*)d_in[6];
    const float* c1_b1  = (const float*)d_in[7];
    const float* c1_w2  = (const float*)d_in[8];
    const float* c1_b2  = (const float*)d_in[9];
    const float* h1_lw  = (const float*)d_in[10];
    const float* h1_w1  = (const float*)d_in[11];
    const float* h1_b1  = (const float*)d_in[12];
    const float* h1_w2  = (const float*)d_in[13];
    const float* h1_b2  = (const float*)d_in[14];
    const float* h2_lw  = (const float*)d_in[15];
    const float* h2_w1  = (const float*)d_in[16];
    const float* h2_b1  = (const float*)d_in[17];
    const float* h2_w2  = (const float*)d_in[18];
    const float* h2_b2  = (const float*)d_in[19];
    const float* lin_w  = (const float*)d_in[20];
    const float* lin_b  = (const float*)d_in[21];

    const int* row = ei;
    const int* col = ei + EE;

    float *A, *B, *C, *D, *XL;
    double* BN;
    cudaGetSymbolAddress((void**)&A,  g_bufA);
    cudaGetSymbolAddress((void**)&B,  g_bufB);
    cudaGetSymbolAddress((void**)&C,  g_bufC);
    cudaGetSymbolAddress((void**)&D,  g_bufD);
    cudaGetSymbolAddress((void**)&XL, g_xl);
    cudaGetSymbolAddress((void**)&BN, g_bn);

    const int EB = (EE + 255) / 256;           // 3125
    const int ZB = (NN * 8 + 255) / 256;       // 1563

    k_zero<<<ZB, 256>>>();

    MlpAll mp;
    mp.p[0] = {c1_w1, c1_b1, c1_w2, c1_b2};
    for (int i = 0; i < 3; i++) {
        mp.p[1 + i] = {h1_w1 + i * FE * FE, h1_b1 + i * FE, h1_w2 + i * FE, h1_b2 + i};
        mp.p[4 + i] = {h2_w1 + i * FE * FE, h2_b1 + i * FE, h2_w2 + i * FE, h2_b2 + i};
    }
    k_mlp<<<EB, 256>>>(ea, col, mp);
    k_scan<<<1, 1024>>>();
    k_dis<<<ZB, 256>>>();
    k_fillnorm<<<EB, 256>>>(row, col);

    const int GEMM_B = (NN + 63) / 64;   // 782
    const int GATH_B = NN / 16;          // 3125

    // conv0 -> x0 in A  (stats for conv1 input)
    k_gemm<<<GEMM_B, 256>>>(x, c1_lw, XL, nullptr);
    k_gather<<<GATH_B, 512>>>(0, (const float2*)XL, A, nullptr, nullptr, nullptr, 0, 0);
    // h1 stack
    k_gemm<<<GEMM_B, 256>>>(A, h1_lw + 0 * CC * CC, XL, BN + 0 * 128);
    k_gather<<<GATH_B, 512>>>(1, (const float2*)XL, B, nullptr, nullptr, nullptr, 0, 1);
    k_gemm<<<GEMM_B, 256>>>(B, h1_lw + 1 * CC * CC, XL, BN + 1 * 128);
    k_gather<<<GATH_B, 512>>>(2, (const float2*)XL, C, nullptr, nullptr, nullptr, 0, 2);
    k_gemm<<<GEMM_B, 256>>>(C, h1_lw + 2 * CC * CC, XL, BN + 2 * 128);
    k_gather<<<GATH_B, 512>>>(3, (const float2*)XL, D, A, nullptr, nullptr, 1, 3);   // D = x1 = out + x0
    // h2 stack
    k_gemm<<<GEMM_B, 256>>>(D, h2_lw + 0 * CC * CC, XL, BN + 3 * 128);
    k_gather<<<GATH_B, 512>>>(4, (const float2*)XL, B, nullptr, nullptr, nullptr, 0, 4);
    k_gemm<<<GEMM_B, 256>>>(B, h2_lw + 1 * CC * CC, XL, BN + 4 * 128);
    k_gather<<<GATH_B, 512>>>(5, (const float2*)XL, C, nullptr, nullptr, nullptr, 0, 5);
    k_gemm<<<GEMM_B, 256>>>(C, h2_lw + 2 * CC * CC, XL, BN + 5 * 128);
    k_gather<<<GATH_B, 512>>>(6, (const float2*)XL, nullptr, A, D, batch, 2, -1);    // pool
    k_fin<<<2, 256>>>(lin_w, lin_b, (float*)d_out);
}